// round 11
// baseline (speedup 1.0000x reference)
#include <cuda_runtime.h>
#include <cuda_fp16.h>
#include <stdint.h>

#define NPIX 16800
#define REG_BASE 2688000L
#define CTR_BASE 3225600L

// static device scratch (no cudaMalloc anywhere). Per-level regions inside
// each buffer: level l at SOFF[l], size 8*256*HW_l floats.
#define BUF_FLOATS 34406400L
__device__ float    g_A[BUF_FLOATS];   // cls conv1 out
__device__ float    g_B[BUF_FLOATS];   // cls conv2 out
__device__ float    g_C[BUF_FLOATS];   // reg conv1 out
__device__ float    g_D[BUF_FLOATS];   // reg conv2 out
__device__ uint32_t g_W[1474560];      // fragment-ordered half2 weights
__device__ float    g_mean[768];       // [tower*3+level][n*16+g]
__device__ float    g_rstd[768];

__device__ __forceinline__ uint32_t smem_u32(const void* p) {
    uint32_t a;
    asm("{ .reg .u64 t; cvta.to.shared.u64 t, %1; cvt.u32.u64 %0, t; }" : "=r"(a) : "l"(p));
    return a;
}
__device__ __forceinline__ void mma16(float* c, const uint32_t* a, uint32_t b0, uint32_t b1) {
    asm volatile(
        "mma.sync.aligned.m16n8k16.row.col.f32.f16.f16.f32 "
        "{%0,%1,%2,%3}, {%4,%5,%6,%7}, {%8,%9}, {%0,%1,%2,%3};"
        : "+f"(c[0]), "+f"(c[1]), "+f"(c[2]), "+f"(c[3])
        : "r"(a[0]), "r"(a[1]), "r"(a[2]), "r"(a[3]), "r"(b0), "r"(b1));
}
__device__ __forceinline__ void ldsm4(uint32_t* r, uint32_t addr) {
    asm volatile("ldmatrix.sync.aligned.m8n8.x4.shared.b16 {%0,%1,%2,%3}, [%4];"
        : "=r"(r[0]), "=r"(r[1]), "=r"(r[2]), "=r"(r[3]) : "r"(addr));
}

// ---------------------------------------------------------------------------
// Merged fp16 mma.sync conv3x3 s1p1 (NCHW). R11: B fragments are register
// double-buffered — the ldmatrix for step i+1 issues BEFORE the 4 MMAs of
// step i, hiding ldsm latency behind tensor work (asm volatile enforces
// program order, so pipelining must be explicit in source).
// Tower stages: 512-thread CTAs (both oc-tiles share one staged halo).
//  STAGE 0: conv1 (no GN), feats -> A/C
//  STAGE 1: conv2 (GN layer0 fused), A/C -> B/D
//  STAGE 2: heads (GN layer1 fused), B/D -> final output
// ---------------------------------------------------------------------------
template<int STAGE, int NW>
__global__ __launch_bounds__(NW * 32, NW == 8 ? 2 : 1)
void conv_mma(const float* __restrict__ f0, const float* __restrict__ f1,
              const float* __restrict__ f2, const uint32_t* __restrict__ wAll,
              const float* __restrict__ b_cls, const float* __restrict__ b_reg,
              const float* __restrict__ b_ctr,
              const float* __restrict__ g_cls, const float* __restrict__ be_cls,
              const float* __restrict__ g_reg, const float* __restrict__ be_reg,
              float* __restrict__ out_cls, float* __restrict__ out_reg)
{
    constexpr int THREADS = NW * 32;
    // ---- level decode ----
    const int bx = blockIdx.x;
    int l, tile, H, W, wt;
    if (bx < 100)      { l = 0; tile = bx;       H = 100; W = 128; wt = 4; }
    else if (bx < 126) { l = 1; tile = bx - 100; H = 50;  W = 64;  wt = 2; }
    else               { l = 2; tile = bx - 126; H = 25;  W = 32;  wt = 1; }
    const int HW = H * W;
    const long SOFF[3]  = { 0L, 26214400L, 32768000L };
    const int  OOFF[3]  = { 0, 12800, 16000 };

    const int tid = threadIdx.x, wid = tid >> 5, lane = tid & 31;
    const int iw = wid & 7;                 // warp index within oc-tile group
    const int g = lane >> 2, t = lane & 3;
    const int wm = iw & 3, wn = iw >> 2;
    const int n = blockIdx.z;

    // ---- tower / oc-tile decode ----
    const int tower  = blockIdx.y;
    const int ocTile = (NW == 16) ? (wid >> 3) : 0;
    const int OCv = (STAGE == 2) ? (tower ? 5 : 20) : 256;
    const int ocBase = ocTile * 128;
    const int x0 = (tile % wt) << 5;
    const int y0 = (tile / wt) << 2;
    const bool active = (ocBase + wm * 32) < OCv;

    __shared__ uint32_t halo[2][4080];   // 204 px * 20 words, double-buffered

    // ldmatrix per-lane base addresses
    const int mm = lane >> 3, rr = lane & 7;
    const uint32_t sbase = smem_u32(halo);
    uint32_t bAddr[4];
#pragma unroll
    for (int p = 0; p < 4; ++p) {
        int pxl = wn * 64 + (2 * p + (mm >> 1)) * 8 + rr;
        bAddr[p] = sbase + (uint32_t)((((pxl >> 5) * 34 + (pxl & 31)) * 20 + (mm & 1) * 4) * 4);
    }

    float acc[2][8][4];
#pragma unroll
    for (int i = 0; i < 2; ++i)
#pragma unroll
        for (int j = 0; j < 8; ++j)
#pragma unroll
            for (int q = 0; q < 4; ++q) acc[i][j][q] = 0.f;

    // ---- input / weight / GN pointers ----
    const float* inL;
    if (STAGE == 0) inL = ((l == 0) ? f0 : (l == 1) ? f1 : f2) + (long)n * 256 * HW;
    else            inL = (tower ? f1 : f0) + SOFF[l] + (long)n * 256 * HW;
    const uint32_t* wA;
    if (STAGE == 0)      wA = wAll + tower * 589824;
    else if (STAGE == 1) wA = wAll + tower * 589824 + 294912;
    else                 wA = wAll + 1179648 + tower * 147456;
    const uint4* __restrict__ wf4 = (const uint4*)(wA + (long)ocTile * 147456);
    const float* gamma = tower ? g_reg : g_cls;
    const float* beta  = tower ? be_reg : be_cls;
    const int meanBase = (tower * 3 + l) * 128 + n * 16;

    // raw load of one staging item (no math; predicated)
    auto stage_ld = [&](int chunk, int i, float& v0, float& v1) {
        int w = i / 204; int px = i - w * 204;
        int ri = px / 34, ci = px - ri * 34;
        int ygl = y0 + ri - 1, xgl = x0 + ci - 1;
        v0 = 0.f; v1 = 0.f;
        if ((unsigned)ygl < (unsigned)H && (unsigned)xgl < (unsigned)W) {
            const float* inC = inL + (long)chunk * 32 * HW;
            long bidx = (long)(2 * w) * HW + (long)ygl * W + xgl;
            v0 = inC[bidx];
            v1 = inC[bidx + HW];
        }
    };
    // GN + pack + STS of one staging item
    auto stage_st = [&](int chunk, int hb, int i, float v0, float v1) {
        int w = i / 204; int px = i - w * 204;
        if (STAGE > 0) {
            int ri = px / 34, ci = px - ri * 34;
            int ygl = y0 + ri - 1, xgl = x0 + ci - 1;
            if ((unsigned)ygl < (unsigned)H && (unsigned)xgl < (unsigned)W) {
                int c = chunk * 32 + 2 * w;
                int sg = meanBase + (c >> 4);
                float m = g_mean[sg], rs = g_rstd[sg];
                v0 = fmaxf((v0 - m) * rs * gamma[c]     + beta[c],     0.f);
                v1 = fmaxf((v1 - m) * rs * gamma[c + 1] + beta[c + 1], 0.f);
            }
        }
        __half2 h = __floats2half2_rn(v0, v1);
        halo[hb][px * 20 + w] = *(uint32_t*)&h;
    };

    // ---- prologue: chunk-0 halo (immediate), tap-0 A fragments ----
    for (int i = tid; i < 3264; i += THREADS) {
        float v0, v1;
        stage_ld(0, i, v0, v1);
        stage_st(0, 0, i, v0, v1);
    }
    uint4 Ac[4];
    if (active) {
#pragma unroll
        for (int q = 0; q < 4; ++q)
            Ac[q] = wf4[(q >> 1) * 256 + (wm * 2 + (q & 1)) * 32 + lane];
    }
    __syncthreads();

    for (int chunk = 0; chunk < 8; ++chunk) {
        const int hb = chunk & 1;
        const uint32_t hoff = (uint32_t)hb * 16320u;
        for (int tap = 0; tap < 9; ++tap) {
            const int cid = chunk * 9 + tap;

            // ---- staging LOAD phase: issue global loads early ----
            float s0a = 0.f, s1a = 0.f, s0b = 0.f, s1b = 0.f;
            int i0 = -1, i1 = -1;
            if (chunk < 7) {
                int lo = tap * 368;
                int hi = lo + 368; if (hi > 3264) hi = 3264;
                int ia = lo + tid;
                if (ia < hi) { i0 = ia; stage_ld(chunk + 1, ia, s0a, s1a); }
                if (THREADS < 368) {
                    int ib = ia + THREADS;
                    if (ib < hi) { i1 = ib; stage_ld(chunk + 1, ib, s0b, s1b); }
                }
            }
            // ---- A prefetch for next tap ----
            uint4 An[4];
            if (active && cid < 71) {
                const uint4* wf = wf4 + (long)(cid + 1) * 512;
#pragma unroll
                for (int q = 0; q < 4; ++q)
                    An[q] = wf[(q >> 1) * 256 + (wm * 2 + (q & 1)) * 32 + lane];
            }
            // ---- MMA block: B-fragment register double-buffer pipeline ----
            if (active) {
                const uint32_t toff = hoff + (uint32_t)(((tap / 3) * 34 + (tap % 3)) * 80);
                uint32_t bf[2][4];
                ldsm4(bf[0], bAddr[0] + toff);          // step 0: ks=0,p=0
#pragma unroll
                for (int s = 0; s < 8; ++s) {           // s = ks*4 + p
                    if (s < 7) {
                        int s1 = s + 1;
                        ldsm4(bf[(s + 1) & 1], bAddr[s1 & 3] + toff + (s1 >> 2) * 32);
                    }
                    const uint32_t* b = bf[s & 1];
                    const int ks = s >> 2, p = s & 3;
                    mma16(acc[0][2 * p],     (const uint32_t*)&Ac[ks * 2],     b[0], b[1]);
                    mma16(acc[1][2 * p],     (const uint32_t*)&Ac[ks * 2 + 1], b[0], b[1]);
                    mma16(acc[0][2 * p + 1], (const uint32_t*)&Ac[ks * 2],     b[2], b[3]);
                    mma16(acc[1][2 * p + 1], (const uint32_t*)&Ac[ks * 2 + 1], b[2], b[3]);
                }
            }
            // ---- staging STORE phase: data arrived during MMAs ----
            if (i0 >= 0) stage_st(chunk + 1, hb ^ 1, i0, s0a, s1a);
            if (THREADS < 368 && i1 >= 0) stage_st(chunk + 1, hb ^ 1, i1, s0b, s1b);
            if (active && cid < 71) {
                Ac[0] = An[0]; Ac[1] = An[1]; Ac[2] = An[2]; Ac[3] = An[3];
            }
        }
        __syncthreads();
    }

    if (!active) return;

    // ---- epilogue ----
#pragma unroll
    for (int mbi = 0; mbi < 2; ++mbi) {
        const int ocl = (wm * 2 + mbi) * 16 + g;
        const int oc = ocBase + ocl;
        if (STAGE < 2) {
            float* outBase = (tower ? out_reg : out_cls) + SOFF[l];
            const float* bias = tower ? b_reg : b_cls;
            const float bv0 = bias[oc], bv1 = bias[oc + 8];
            float* o0 = outBase + ((long)n * 256 + oc) * HW;
#pragma unroll
            for (int nb = 0; nb < 8; ++nb) {
                int pxl = wn * 64 + nb * 8 + 2 * t;
                int ygl = y0 + (pxl >> 5);
                if (ygl >= H) continue;
                long idx = (long)ygl * W + x0 + (pxl & 31);
                *(float2*)(o0 + idx) =
                    make_float2(acc[mbi][nb][0] + bv0, acc[mbi][nb][1] + bv0);
                *(float2*)(o0 + 8L * HW + idx) =
                    make_float2(acc[mbi][nb][2] + bv1, acc[mbi][nb][3] + bv1);
            }
        } else if (tower == 0) {   // cls head
            float* out = out_cls;
#pragma unroll
            for (int nb = 0; nb < 8; ++nb) {
                int pxl = wn * 64 + nb * 8 + 2 * t;
                int ygl = y0 + (pxl >> 5);
                if (ygl >= H) continue;
                int pxg = ygl * W + x0 + (pxl & 31);
                long b = ((long)n * NPIX + OOFF[l] + pxg) * 20;
                if (oc < 20) {
                    float bv = b_cls[oc];
                    out[b + oc]      = acc[mbi][nb][0] + bv;
                    out[b + 20 + oc] = acc[mbi][nb][1] + bv;
                }
                if (oc + 8 < 20) {
                    float bv = b_cls[oc + 8];
                    out[b + oc + 8]      = acc[mbi][nb][2] + bv;
                    out[b + 20 + oc + 8] = acc[mbi][nb][3] + bv;
                }
            }
        } else {                   // reg + ctr head
            float* out = out_reg;
#pragma unroll
            for (int nb = 0; nb < 8; ++nb) {
                int pxl = wn * 64 + nb * 8 + 2 * t;
                int ygl = y0 + (pxl >> 5);
                if (ygl >= H) continue;
                int pxg = ygl * W + x0 + (pxl & 31);
#pragma unroll
                for (int rrj = 0; rrj < 2; ++rrj) {
                    int ocr = oc + rrj * 8;
                    float v0 = acc[mbi][nb][rrj * 2 + 0];
                    float v1 = acc[mbi][nb][rrj * 2 + 1];
                    if (ocr < 4) {
                        float bv = b_reg[ocr];
                        long rb = REG_BASE + (long)n * 67200 + (long)(OOFF[l] + pxg) * 4 + ocr;
                        out[rb]     = fmaxf(v0 + bv, 0.f);
                        out[rb + 4] = fmaxf(v1 + bv, 0.f);
                    } else if (ocr == 4) {
                        float bv = b_ctr[0];
                        long cb = CTR_BASE + (long)n * NPIX + OOFF[l] + pxg;
                        out[cb]     = v0 + bv;
                        out[cb + 1] = v1 + bv;
                    }
                }
            }
        }
    }
}

// ---------------------------------------------------------------------------
// Weight reorders -> fragment-linear half2 (unchanged layout).
// ---------------------------------------------------------------------------
__device__ __forceinline__ void frag_decode(int d, int& r, int& chunk, int& tap,
                                            int& oc128, int& icp)
{
    int j = d & 3; int q = d >> 2;
    int lane = q & 31; q >>= 5;
    int mb = q & 7;  q >>= 3;
    int ks = q & 1;  q >>= 1;
    tap = q % 9; q /= 9;
    chunk = q & 7; q >>= 3;
    r = q;
    oc128 = mb * 16 + (lane >> 2) + (j & 1) * 8;
    icp   = chunk * 32 + ks * 16 + (lane & 3) * 2 + ((j >> 1) & 1) * 8;
}

__global__ void reorder_tower(const float* __restrict__ w, uint32_t* __restrict__ dst)
{
    int d = blockIdx.x * 256 + threadIdx.x;
    if (d >= 589824) return;
    int r, chunk, tap, oc128, icp;
    frag_decode(d, r, chunk, tap, oc128, icp);
    int layer = r >> 1;
    int oc = (r & 1) * 128 + oc128;
    const float* src = w + (long)layer * 589824;
    float v0 = src[((long)oc * 256 + icp) * 9 + tap];
    float v1 = src[((long)oc * 256 + icp + 1) * 9 + tap];
    __half2 h = __floats2half2_rn(v0, v1);
    dst[d] = *(uint32_t*)&h;
}

__global__ void reorder_heads(const float* __restrict__ wcls, const float* __restrict__ wreg,
                              const float* __restrict__ wctr, uint32_t* __restrict__ dst)
{
    int d = blockIdx.x * 256 + threadIdx.x;
    if (d >= 294912) return;
    int r, chunk, tap, oc128, icp;
    frag_decode(d, r, chunk, tap, oc128, icp);
    int oc = oc128;
    float v0 = 0.f, v1 = 0.f;
    if (r == 0) {
        if (oc < 20) {
            v0 = wcls[((long)oc * 256 + icp) * 9 + tap];
            v1 = wcls[((long)oc * 256 + icp + 1) * 9 + tap];
        }
    } else {
        if (oc < 4) {
            v0 = wreg[((long)oc * 256 + icp) * 9 + tap];
            v1 = wreg[((long)oc * 256 + icp + 1) * 9 + tap];
        } else if (oc == 4) {
            v0 = wctr[(long)icp * 9 + tap];
            v1 = wctr[(long)(icp + 1) * 9 + tap];
        }
    }
    __half2 h = __floats2half2_rn(v0, v1);
    dst[d] = *(uint32_t*)&h;
}

// ---------------------------------------------------------------------------
// GroupNorm stats for all (tower, level) pairs in one launch.
// ---------------------------------------------------------------------------
__global__ void gn_stats_all(const float* __restrict__ bufCls, const float* __restrict__ bufReg)
{
    const int by = blockIdx.y;
    const int tower = by / 3, l = by - tower * 3;
    const int HWs[3] = { 12800, 3200, 800 };
    const long SOFF[3] = { 0L, 26214400L, 32768000L };
    const int HW = HWs[l];
    const int n = blockIdx.x >> 4;
    const int g = blockIdx.x & 15;
    const float4* p = (const float4*)((tower ? bufReg : bufCls) + SOFF[l]
                                      + ((long)n * 256 + (long)g * 16) * HW);
    const int total4 = (16 * HW) >> 2;
    float s = 0.f, s2 = 0.f;
    for (int i = threadIdx.x; i < total4; i += blockDim.x) {
        float4 v = p[i];
        s  += v.x + v.y + v.z + v.w;
        s2 += v.x * v.x + v.y * v.y + v.z * v.z + v.w * v.w;
    }
    __shared__ float rs[8], rs2[8];
#pragma unroll
    for (int o = 16; o; o >>= 1) {
        s  += __shfl_xor_sync(~0u, s, o);
        s2 += __shfl_xor_sync(~0u, s2, o);
    }
    const int w = threadIdx.x >> 5, lid = threadIdx.x & 31;
    if (lid == 0) { rs[w] = s; rs2[w] = s2; }
    __syncthreads();
    if (w == 0) {
        s  = (lid < 8) ? rs[lid]  : 0.f;
        s2 = (lid < 8) ? rs2[lid] : 0.f;
#pragma unroll
        for (int o = 4; o; o >>= 1) {
            s  += __shfl_xor_sync(~0u, s, o);
            s2 += __shfl_xor_sync(~0u, s2, o);
        }
        if (lid == 0) {
            float inv = 1.f / (float)(16 * HW);
            float m = s * inv;
            g_mean[by * 128 + blockIdx.x] = m;
            g_rstd[by * 128 + blockIdx.x] = rsqrtf(s2 * inv - m * m + 1e-5f);
        }
    }
}

// ---------------------------------------------------------------------------
extern "C" void kernel_launch(void* const* d_in, const int* in_sizes, int n_in,
                              void* d_out, int out_size)
{
    (void)in_sizes; (void)n_in; (void)out_size;
    const float* feat0 = (const float*)d_in[0];
    const float* feat1 = (const float*)d_in[1];
    const float* feat2 = (const float*)d_in[2];
    const float* cls_conv_w = (const float*)d_in[3];
    const float* cls_conv_b = (const float*)d_in[4];
    const float* cls_gn_g = (const float*)d_in[5];
    const float* cls_gn_b = (const float*)d_in[6];
    const float* cls_out_w = (const float*)d_in[7];
    const float* cls_out_b = (const float*)d_in[8];
    const float* reg_conv_w = (const float*)d_in[9];
    const float* reg_conv_b = (const float*)d_in[10];
    const float* reg_gn_g = (const float*)d_in[11];
    const float* reg_gn_b = (const float*)d_in[12];
    const float* reg_out_w = (const float*)d_in[13];
    const float* reg_out_b = (const float*)d_in[14];
    const float* ctr_w = (const float*)d_in[15];
    const float* ctr_b = (const float*)d_in[16];
    float* out = (float*)d_out;

    float *pA, *pB, *pC, *pD;
    uint32_t* pW;
    cudaGetSymbolAddress((void**)&pA, g_A);
    cudaGetSymbolAddress((void**)&pB, g_B);
    cudaGetSymbolAddress((void**)&pC, g_C);
    cudaGetSymbolAddress((void**)&pD, g_D);
    cudaGetSymbolAddress((void**)&pW, g_W);

    // weight reorders
    reorder_tower<<<2304, 256>>>(cls_conv_w, pW);
    reorder_tower<<<2304, 256>>>(reg_conv_w, pW + 589824);
    reorder_heads<<<1152, 256>>>(cls_out_w, reg_out_w, ctr_w, pW + 1179648);

    // stage 1: conv1 (both towers, all levels; 512-thread CTAs, both oc tiles)
    conv_mma<0, 16><<<dim3(133, 2, 8), 512>>>(feat0, feat1, feat2, pW,
                                              cls_conv_b, reg_conv_b, nullptr,
                                              nullptr, nullptr, nullptr, nullptr,
                                              pA, pC);
    gn_stats_all<<<dim3(128, 6), 256>>>(pA, pC);

    // stage 2: conv2 (GN layer0 fused)
    conv_mma<1, 16><<<dim3(133, 2, 8), 512>>>(pA, pC, nullptr, pW,
                                              cls_conv_b + 256, reg_conv_b + 256, nullptr,
                                              cls_gn_g, cls_gn_b, reg_gn_g, reg_gn_b,
                                              pB, pD);
    gn_stats_all<<<dim3(128, 6), 256>>>(pB, pD);

    // stage 3: heads (GN layer1 fused; 256-thread CTAs)
    conv_mma<2, 8><<<dim3(133, 2, 8), 256>>>(pB, pD, nullptr, pW,
                                             cls_out_b, reg_out_b, ctr_b,
                                             cls_gn_g + 256, cls_gn_b + 256,
                                             reg_gn_g + 256, reg_gn_b + 256,
                                             out, out);
}

// round 12
// speedup vs baseline: 1.4773x; 1.4773x over previous
#include <cuda_runtime.h>
#include <cuda_fp16.h>
#include <stdint.h>

#define NPIX 16800
#define REG_BASE 2688000L
#define CTR_BASE 3225600L

// static device scratch (no cudaMalloc anywhere). Per-level regions inside
// each buffer: level l at SOFF[l], size 8*256*HW_l floats.
#define BUF_FLOATS 34406400L
__device__ float    g_A[BUF_FLOATS];   // cls conv1 out
__device__ float    g_B[BUF_FLOATS];   // cls conv2 out
__device__ float    g_C[BUF_FLOATS];   // reg conv1 out
__device__ float    g_D[BUF_FLOATS];   // reg conv2 out
__device__ uint32_t g_W[1474560];      // fragment-ordered half2 weights
__device__ float    g_mean[768];       // [tower*3+level][n*16+g]
__device__ float    g_rstd[768];

__device__ __forceinline__ uint32_t smem_u32(const void* p) {
    uint32_t a;
    asm("{ .reg .u64 t; cvta.to.shared.u64 t, %1; cvt.u32.u64 %0, t; }" : "=r"(a) : "l"(p));
    return a;
}
__device__ __forceinline__ void mma16(float* c, const uint32_t* a, uint32_t b0, uint32_t b1) {
    asm volatile(
        "mma.sync.aligned.m16n8k16.row.col.f32.f16.f16.f32 "
        "{%0,%1,%2,%3}, {%4,%5,%6,%7}, {%8,%9}, {%0,%1,%2,%3};"
        : "+f"(c[0]), "+f"(c[1]), "+f"(c[2]), "+f"(c[3])
        : "r"(a[0]), "r"(a[1]), "r"(a[2]), "r"(a[3]), "r"(b0), "r"(b1));
}
__device__ __forceinline__ void ldsm4(uint32_t* r, uint32_t addr) {
    asm volatile("ldmatrix.sync.aligned.m8n8.x4.shared.b16 {%0,%1,%2,%3}, [%4];"
        : "=r"(r[0]), "=r"(r[1]), "=r"(r[2]), "=r"(r[3]) : "r"(addr));
}

// ---------------------------------------------------------------------------
// Merged fp16 mma.sync conv3x3 s1p1 (NCHW). R12 = R10 inner loop (the R11
// B double-buffer spilled registers at the 128-reg cap and regressed) plus
// a head-stage warp remap: for STAGE==2 the MMA-active warps (wm==0) were
// wid 0 and 4 — both SMSP 0. Remap wm=wid>>1, wn=wid&1 puts them on SMSP
// 0 and 1 (same oc/px coverage, zero extra registers).
// Tower stages: 512-thread CTAs (both oc-tiles share one staged halo).
//  STAGE 0: conv1 (no GN), feats -> A/C
//  STAGE 1: conv2 (GN layer0 fused), A/C -> B/D
//  STAGE 2: heads (GN layer1 fused), B/D -> final output
// ---------------------------------------------------------------------------
template<int STAGE, int NW>
__global__ __launch_bounds__(NW * 32, NW == 8 ? 2 : 1)
void conv_mma(const float* __restrict__ f0, const float* __restrict__ f1,
              const float* __restrict__ f2, const uint32_t* __restrict__ wAll,
              const float* __restrict__ b_cls, const float* __restrict__ b_reg,
              const float* __restrict__ b_ctr,
              const float* __restrict__ g_cls, const float* __restrict__ be_cls,
              const float* __restrict__ g_reg, const float* __restrict__ be_reg,
              float* __restrict__ out_cls, float* __restrict__ out_reg)
{
    constexpr int THREADS = NW * 32;
    // ---- level decode ----
    const int bx = blockIdx.x;
    int l, tile, H, W, wt;
    if (bx < 100)      { l = 0; tile = bx;       H = 100; W = 128; wt = 4; }
    else if (bx < 126) { l = 1; tile = bx - 100; H = 50;  W = 64;  wt = 2; }
    else               { l = 2; tile = bx - 126; H = 25;  W = 32;  wt = 1; }
    const int HW = H * W;
    const long SOFF[3]  = { 0L, 26214400L, 32768000L };
    const int  OOFF[3]  = { 0, 12800, 16000 };

    const int tid = threadIdx.x, wid = tid >> 5, lane = tid & 31;
    const int iw = wid & 7;                 // warp index within oc-tile group
    const int g = lane >> 2, t = lane & 3;
    // head stage: active (wm==0) warps land on different SMSPs
    const int wm = (STAGE == 2) ? (iw >> 1) : (iw & 3);
    const int wn = (STAGE == 2) ? (iw & 1) : (iw >> 2);
    const int n = blockIdx.z;

    // ---- tower / oc-tile decode ----
    const int tower  = blockIdx.y;
    const int ocTile = (NW == 16) ? (wid >> 3) : 0;
    const int OCv = (STAGE == 2) ? (tower ? 5 : 20) : 256;
    const int ocBase = ocTile * 128;
    const int x0 = (tile % wt) << 5;
    const int y0 = (tile / wt) << 2;
    const bool active = (ocBase + wm * 32) < OCv;

    __shared__ uint32_t halo[2][4080];   // 204 px * 20 words, double-buffered

    // ldmatrix per-lane base addresses
    const int mm = lane >> 3, rr = lane & 7;
    const uint32_t sbase = smem_u32(halo);
    uint32_t bAddr[4];
#pragma unroll
    for (int p = 0; p < 4; ++p) {
        int pxl = wn * 64 + (2 * p + (mm >> 1)) * 8 + rr;
        bAddr[p] = sbase + (uint32_t)((((pxl >> 5) * 34 + (pxl & 31)) * 20 + (mm & 1) * 4) * 4);
    }

    float acc[2][8][4];
#pragma unroll
    for (int i = 0; i < 2; ++i)
#pragma unroll
        for (int j = 0; j < 8; ++j)
#pragma unroll
            for (int q = 0; q < 4; ++q) acc[i][j][q] = 0.f;

    // ---- input / weight / GN pointers ----
    const float* inL;
    if (STAGE == 0) inL = ((l == 0) ? f0 : (l == 1) ? f1 : f2) + (long)n * 256 * HW;
    else            inL = (tower ? f1 : f0) + SOFF[l] + (long)n * 256 * HW;
    const uint32_t* wA;
    if (STAGE == 0)      wA = wAll + tower * 589824;
    else if (STAGE == 1) wA = wAll + tower * 589824 + 294912;
    else                 wA = wAll + 1179648 + tower * 147456;
    const uint4* __restrict__ wf4 = (const uint4*)(wA + (long)ocTile * 147456);
    const float* gamma = tower ? g_reg : g_cls;
    const float* beta  = tower ? be_reg : be_cls;
    const int meanBase = (tower * 3 + l) * 128 + n * 16;

    // raw load of one staging item (no math; predicated)
    auto stage_ld = [&](int chunk, int i, float& v0, float& v1) {
        int w = i / 204; int px = i - w * 204;
        int ri = px / 34, ci = px - ri * 34;
        int ygl = y0 + ri - 1, xgl = x0 + ci - 1;
        v0 = 0.f; v1 = 0.f;
        if ((unsigned)ygl < (unsigned)H && (unsigned)xgl < (unsigned)W) {
            const float* inC = inL + (long)chunk * 32 * HW;
            long bidx = (long)(2 * w) * HW + (long)ygl * W + xgl;
            v0 = inC[bidx];
            v1 = inC[bidx + HW];
        }
    };
    // GN + pack + STS of one staging item
    auto stage_st = [&](int chunk, int hb, int i, float v0, float v1) {
        int w = i / 204; int px = i - w * 204;
        if (STAGE > 0) {
            int ri = px / 34, ci = px - ri * 34;
            int ygl = y0 + ri - 1, xgl = x0 + ci - 1;
            if ((unsigned)ygl < (unsigned)H && (unsigned)xgl < (unsigned)W) {
                int c = chunk * 32 + 2 * w;
                int sg = meanBase + (c >> 4);
                float m = g_mean[sg], rs = g_rstd[sg];
                v0 = fmaxf((v0 - m) * rs * gamma[c]     + beta[c],     0.f);
                v1 = fmaxf((v1 - m) * rs * gamma[c + 1] + beta[c + 1], 0.f);
            }
        }
        __half2 h = __floats2half2_rn(v0, v1);
        halo[hb][px * 20 + w] = *(uint32_t*)&h;
    };

    // ---- prologue: chunk-0 halo (immediate), tap-0 A fragments ----
    for (int i = tid; i < 3264; i += THREADS) {
        float v0, v1;
        stage_ld(0, i, v0, v1);
        stage_st(0, 0, i, v0, v1);
    }
    uint4 Ac[4];
    if (active) {
#pragma unroll
        for (int q = 0; q < 4; ++q)
            Ac[q] = wf4[(q >> 1) * 256 + (wm * 2 + (q & 1)) * 32 + lane];
    }
    __syncthreads();

    for (int chunk = 0; chunk < 8; ++chunk) {
        const int hb = chunk & 1;
        const uint32_t hoff = (uint32_t)hb * 16320u;
        for (int tap = 0; tap < 9; ++tap) {
            const int cid = chunk * 9 + tap;

            // ---- staging LOAD phase: issue global loads early ----
            float s0a = 0.f, s1a = 0.f, s0b = 0.f, s1b = 0.f;
            int i0 = -1, i1 = -1;
            if (chunk < 7) {
                int lo = tap * 368;
                int hi = lo + 368; if (hi > 3264) hi = 3264;
                int ia = lo + tid;
                if (ia < hi) { i0 = ia; stage_ld(chunk + 1, ia, s0a, s1a); }
                if (THREADS < 368) {
                    int ib = ia + THREADS;
                    if (ib < hi) { i1 = ib; stage_ld(chunk + 1, ib, s0b, s1b); }
                }
            }
            // ---- A prefetch for next tap ----
            uint4 An[4];
            if (active && cid < 71) {
                const uint4* wf = wf4 + (long)(cid + 1) * 512;
#pragma unroll
                for (int q = 0; q < 4; ++q)
                    An[q] = wf[(q >> 1) * 256 + (wm * 2 + (q & 1)) * 32 + lane];
            }
            // ---- MMA block (R10 form: ldsm4 then 4 MMAs, no extra regs) ----
            if (active) {
                const uint32_t toff = hoff + (uint32_t)(((tap / 3) * 34 + (tap % 3)) * 80);
#pragma unroll
                for (int ks = 0; ks < 2; ++ks) {
                    const uint32_t o2 = toff + ks * 32;
#pragma unroll
                    for (int p = 0; p < 4; ++p) {
                        uint32_t b[4];
                        ldsm4(b, bAddr[p] + o2);
                        mma16(acc[0][2 * p],     (const uint32_t*)&Ac[ks * 2],     b[0], b[1]);
                        mma16(acc[1][2 * p],     (const uint32_t*)&Ac[ks * 2 + 1], b[0], b[1]);
                        mma16(acc[0][2 * p + 1], (const uint32_t*)&Ac[ks * 2],     b[2], b[3]);
                        mma16(acc[1][2 * p + 1], (const uint32_t*)&Ac[ks * 2 + 1], b[2], b[3]);
                    }
                }
            }
            // ---- staging STORE phase: data arrived during MMAs ----
            if (i0 >= 0) stage_st(chunk + 1, hb ^ 1, i0, s0a, s1a);
            if (THREADS < 368 && i1 >= 0) stage_st(chunk + 1, hb ^ 1, i1, s0b, s1b);
            if (active && cid < 71) {
                Ac[0] = An[0]; Ac[1] = An[1]; Ac[2] = An[2]; Ac[3] = An[3];
            }
        }
        __syncthreads();
    }

    if (!active) return;

    // ---- epilogue ----
#pragma unroll
    for (int mbi = 0; mbi < 2; ++mbi) {
        const int ocl = (wm * 2 + mbi) * 16 + g;
        const int oc = ocBase + ocl;
        if (STAGE < 2) {
            float* outBase = (tower ? out_reg : out_cls) + SOFF[l];
            const float* bias = tower ? b_reg : b_cls;
            const float bv0 = bias[oc], bv1 = bias[oc + 8];
            float* o0 = outBase + ((long)n * 256 + oc) * HW;
#pragma unroll
            for (int nb = 0; nb < 8; ++nb) {
                int pxl = wn * 64 + nb * 8 + 2 * t;
                int ygl = y0 + (pxl >> 5);
                if (ygl >= H) continue;
                long idx = (long)ygl * W + x0 + (pxl & 31);
                *(float2*)(o0 + idx) =
                    make_float2(acc[mbi][nb][0] + bv0, acc[mbi][nb][1] + bv0);
                *(float2*)(o0 + 8L * HW + idx) =
                    make_float2(acc[mbi][nb][2] + bv1, acc[mbi][nb][3] + bv1);
            }
        } else if (tower == 0) {   // cls head
            float* out = out_cls;
#pragma unroll
            for (int nb = 0; nb < 8; ++nb) {
                int pxl = wn * 64 + nb * 8 + 2 * t;
                int ygl = y0 + (pxl >> 5);
                if (ygl >= H) continue;
                int pxg = ygl * W + x0 + (pxl & 31);
                long b = ((long)n * NPIX + OOFF[l] + pxg) * 20;
                if (oc < 20) {
                    float bv = b_cls[oc];
                    out[b + oc]      = acc[mbi][nb][0] + bv;
                    out[b + 20 + oc] = acc[mbi][nb][1] + bv;
                }
                if (oc + 8 < 20) {
                    float bv = b_cls[oc + 8];
                    out[b + oc + 8]      = acc[mbi][nb][2] + bv;
                    out[b + 20 + oc + 8] = acc[mbi][nb][3] + bv;
                }
            }
        } else {                   // reg + ctr head
            float* out = out_reg;
#pragma unroll
            for (int nb = 0; nb < 8; ++nb) {
                int pxl = wn * 64 + nb * 8 + 2 * t;
                int ygl = y0 + (pxl >> 5);
                if (ygl >= H) continue;
                int pxg = ygl * W + x0 + (pxl & 31);
#pragma unroll
                for (int rrj = 0; rrj < 2; ++rrj) {
                    int ocr = oc + rrj * 8;
                    float v0 = acc[mbi][nb][rrj * 2 + 0];
                    float v1 = acc[mbi][nb][rrj * 2 + 1];
                    if (ocr < 4) {
                        float bv = b_reg[ocr];
                        long rb = REG_BASE + (long)n * 67200 + (long)(OOFF[l] + pxg) * 4 + ocr;
                        out[rb]     = fmaxf(v0 + bv, 0.f);
                        out[rb + 4] = fmaxf(v1 + bv, 0.f);
                    } else if (ocr == 4) {
                        float bv = b_ctr[0];
                        long cb = CTR_BASE + (long)n * NPIX + OOFF[l] + pxg;
                        out[cb]     = v0 + bv;
                        out[cb + 1] = v1 + bv;
                    }
                }
            }
        }
    }
}

// ---------------------------------------------------------------------------
// Weight reorders -> fragment-linear half2 (unchanged layout).
// ---------------------------------------------------------------------------
__device__ __forceinline__ void frag_decode(int d, int& r, int& chunk, int& tap,
                                            int& oc128, int& icp)
{
    int j = d & 3; int q = d >> 2;
    int lane = q & 31; q >>= 5;
    int mb = q & 7;  q >>= 3;
    int ks = q & 1;  q >>= 1;
    tap = q % 9; q /= 9;
    chunk = q & 7; q >>= 3;
    r = q;
    oc128 = mb * 16 + (lane >> 2) + (j & 1) * 8;
    icp   = chunk * 32 + ks * 16 + (lane & 3) * 2 + ((j >> 1) & 1) * 8;
}

__global__ void reorder_tower(const float* __restrict__ w, uint32_t* __restrict__ dst)
{
    int d = blockIdx.x * 256 + threadIdx.x;
    if (d >= 589824) return;
    int r, chunk, tap, oc128, icp;
    frag_decode(d, r, chunk, tap, oc128, icp);
    int layer = r >> 1;
    int oc = (r & 1) * 128 + oc128;
    const float* src = w + (long)layer * 589824;
    float v0 = src[((long)oc * 256 + icp) * 9 + tap];
    float v1 = src[((long)oc * 256 + icp + 1) * 9 + tap];
    __half2 h = __floats2half2_rn(v0, v1);
    dst[d] = *(uint32_t*)&h;
}

__global__ void reorder_heads(const float* __restrict__ wcls, const float* __restrict__ wreg,
                              const float* __restrict__ wctr, uint32_t* __restrict__ dst)
{
    int d = blockIdx.x * 256 + threadIdx.x;
    if (d >= 294912) return;
    int r, chunk, tap, oc128, icp;
    frag_decode(d, r, chunk, tap, oc128, icp);
    int oc = oc128;
    float v0 = 0.f, v1 = 0.f;
    if (r == 0) {
        if (oc < 20) {
            v0 = wcls[((long)oc * 256 + icp) * 9 + tap];
            v1 = wcls[((long)oc * 256 + icp + 1) * 9 + tap];
        }
    } else {
        if (oc < 4) {
            v0 = wreg[((long)oc * 256 + icp) * 9 + tap];
            v1 = wreg[((long)oc * 256 + icp + 1) * 9 + tap];
        } else if (oc == 4) {
            v0 = wctr[(long)icp * 9 + tap];
            v1 = wctr[(long)(icp + 1) * 9 + tap];
        }
    }
    __half2 h = __floats2half2_rn(v0, v1);
    dst[d] = *(uint32_t*)&h;
}

// ---------------------------------------------------------------------------
// GroupNorm stats for all (tower, level) pairs in one launch.
// ---------------------------------------------------------------------------
__global__ void gn_stats_all(const float* __restrict__ bufCls, const float* __restrict__ bufReg)
{
    const int by = blockIdx.y;
    const int tower = by / 3, l = by - tower * 3;
    const int HWs[3] = { 12800, 3200, 800 };
    const long SOFF[3] = { 0L, 26214400L, 32768000L };
    const int HW = HWs[l];
    const int n = blockIdx.x >> 4;
    const int g = blockIdx.x & 15;
    const float4* p = (const float4*)((tower ? bufReg : bufCls) + SOFF[l]
                                      + ((long)n * 256 + (long)g * 16) * HW);
    const int total4 = (16 * HW) >> 2;
    float s = 0.f, s2 = 0.f;
    for (int i = threadIdx.x; i < total4; i += blockDim.x) {
        float4 v = p[i];
        s  += v.x + v.y + v.z + v.w;
        s2 += v.x * v.x + v.y * v.y + v.z * v.z + v.w * v.w;
    }
    __shared__ float rs[8], rs2[8];
#pragma unroll
    for (int o = 16; o; o >>= 1) {
        s  += __shfl_xor_sync(~0u, s, o);
        s2 += __shfl_xor_sync(~0u, s2, o);
    }
    const int w = threadIdx.x >> 5, lid = threadIdx.x & 31;
    if (lid == 0) { rs[w] = s; rs2[w] = s2; }
    __syncthreads();
    if (w == 0) {
        s  = (lid < 8) ? rs[lid]  : 0.f;
        s2 = (lid < 8) ? rs2[lid] : 0.f;
#pragma unroll
        for (int o = 4; o; o >>= 1) {
            s  += __shfl_xor_sync(~0u, s, o);
            s2 += __shfl_xor_sync(~0u, s2, o);
        }
        if (lid == 0) {
            float inv = 1.f / (float)(16 * HW);
            float m = s * inv;
            g_mean[by * 128 + blockIdx.x] = m;
            g_rstd[by * 128 + blockIdx.x] = rsqrtf(s2 * inv - m * m + 1e-5f);
        }
    }
}

// ---------------------------------------------------------------------------
extern "C" void kernel_launch(void* const* d_in, const int* in_sizes, int n_in,
                              void* d_out, int out_size)
{
    (void)in_sizes; (void)n_in; (void)out_size;
    const float* feat0 = (const float*)d_in[0];
    const float* feat1 = (const float*)d_in[1];
    const float* feat2 = (const float*)d_in[2];
    const float* cls_conv_w = (const float*)d_in[3];
    const float* cls_conv_b = (const float*)d_in[4];
    const float* cls_gn_g = (const float*)d_in[5];
    const float* cls_gn_b = (const float*)d_in[6];
    const float* cls_out_w = (const float*)d_in[7];
    const float* cls_out_b = (const float*)d_in[8];
    const float* reg_conv_w = (const float*)d_in[9];
    const float* reg_conv_b = (const float*)d_in[10];
    const float* reg_gn_g = (const float*)d_in[11];
    const float* reg_gn_b = (const float*)d_in[12];
    const float* reg_out_w = (const float*)d_in[13];
    const float* reg_out_b = (const float*)d_in[14];
    const float* ctr_w = (const float*)d_in[15];
    const float* ctr_b = (const float*)d_in[16];
    float* out = (float*)d_out;

    float *pA, *pB, *pC, *pD;
    uint32_t* pW;
    cudaGetSymbolAddress((void**)&pA, g_A);
    cudaGetSymbolAddress((void**)&pB, g_B);
    cudaGetSymbolAddress((void**)&pC, g_C);
    cudaGetSymbolAddress((void**)&pD, g_D);
    cudaGetSymbolAddress((void**)&pW, g_W);

    // weight reorders
    reorder_tower<<<2304, 256>>>(cls_conv_w, pW);
    reorder_tower<<<2304, 256>>>(reg_conv_w, pW + 589824);
    reorder_heads<<<1152, 256>>>(cls_out_w, reg_out_w, ctr_w, pW + 1179648);

    // stage 1: conv1 (both towers, all levels; 512-thread CTAs, both oc tiles)
    conv_mma<0, 16><<<dim3(133, 2, 8), 512>>>(feat0, feat1, feat2, pW,
                                              cls_conv_b, reg_conv_b, nullptr,
                                              nullptr, nullptr, nullptr, nullptr,
                                              pA, pC);
    gn_stats_all<<<dim3(128, 6), 256>>>(pA, pC);

    // stage 2: conv2 (GN layer0 fused)
    conv_mma<1, 16><<<dim3(133, 2, 8), 512>>>(pA, pC, nullptr, pW,
                                              cls_conv_b + 256, reg_conv_b + 256, nullptr,
                                              cls_gn_g, cls_gn_b, reg_gn_g, reg_gn_b,
                                              pB, pD);
    gn_stats_all<<<dim3(128, 6), 256>>>(pB, pD);

    // stage 3: heads (GN layer1 fused; 256-thread CTAs, remapped warps)
    conv_mma<2, 8><<<dim3(133, 2, 8), 256>>>(pB, pD, nullptr, pW,
                                             cls_out_b, reg_out_b, ctr_b,
                                             cls_gn_g + 256, cls_gn_b + 256,
                                             reg_gn_g + 256, reg_gn_b + 256,
                                             out, out);
}

// round 13
// speedup vs baseline: 1.6612x; 1.1245x over previous
#include <cuda_runtime.h>
#include <cuda_fp16.h>
#include <stdint.h>

#define NPIX 16800
#define REG_BASE 2688000L
#define CTR_BASE 3225600L

// static device scratch (no cudaMalloc anywhere)
#define BUF_FLOATS 34406400L
__device__ float    g_A[BUF_FLOATS];    // cls conv1 fp32 out (for stats)
__device__ float    g_B[BUF_FLOATS];    // cls conv2 fp32 out
__device__ float    g_C[BUF_FLOATS];    // reg conv1 fp32 out
__device__ float    g_D[BUF_FLOATS];    // reg conv2 fp32 out
__device__ uint32_t g_PF [17203200];    // packed half2 feats (tower-shared)
__device__ uint32_t g_P1c[17203200];    // packed GN(conv1) cls
__device__ uint32_t g_P1r[17203200];    // packed GN(conv1) reg
__device__ uint32_t g_P2c[17203200];    // packed GN(conv2) cls
__device__ uint32_t g_P2r[17203200];    // packed GN(conv2) reg
__device__ uint32_t g_W[1474560];       // fragment-ordered half2 weights
__device__ float    g_mean[768];        // [tower*3+level][n*16+g]
__device__ float    g_rstd[768];

__device__ __forceinline__ uint32_t smem_u32(const void* p) {
    uint32_t a;
    asm("{ .reg .u64 t; cvta.to.shared.u64 t, %1; cvt.u32.u64 %0, t; }" : "=r"(a) : "l"(p));
    return a;
}
__device__ __forceinline__ void mma16(float* c, const uint32_t* a, uint32_t b0, uint32_t b1) {
    asm volatile(
        "mma.sync.aligned.m16n8k16.row.col.f32.f16.f16.f32 "
        "{%0,%1,%2,%3}, {%4,%5,%6,%7}, {%8,%9}, {%0,%1,%2,%3};"
        : "+f"(c[0]), "+f"(c[1]), "+f"(c[2]), "+f"(c[3])
        : "r"(a[0]), "r"(a[1]), "r"(a[2]), "r"(a[3]), "r"(b0), "r"(b1));
}
__device__ __forceinline__ void ldsm4(uint32_t* r, uint32_t addr) {
    asm volatile("ldmatrix.sync.aligned.m8n8.x4.shared.b16 {%0,%1,%2,%3}, [%4];"
        : "=r"(r[0]), "=r"(r[1]), "=r"(r[2]), "=r"(r[3]) : "r"(addr));
}
#define CP_A4(dst, src, sz) \
    asm volatile("cp.async.ca.shared.global [%0], [%1], 4, %2;" \
                 :: "r"(dst), "l"(src), "r"(sz) : "memory")
#define CP_WAIT_ALL() asm volatile("cp.async.wait_all;" ::: "memory")

// ---------------------------------------------------------------------------
// Merged fp16 mma.sync conv3x3 s1p1. R13: inputs are PRE-PACKED half2
// ([chunk][ic-pair][H][W]); halo staging is a single 4B cp.async per item
// (no GN / cvt / registers in the hot loop). One cp.async.wait_all +
// barrier per chunk. Tower stages: 512-thread CTAs, both oc-tiles share
// the staged halo. STAGE 0/1: conv -> fp32 NCHW scratch. STAGE 2: heads.
// ---------------------------------------------------------------------------
template<int STAGE, int NW>
__global__ __launch_bounds__(NW * 32, NW == 8 ? 2 : 1)
void conv_mma(const uint32_t* __restrict__ pkCls, const uint32_t* __restrict__ pkReg,
              const uint32_t* __restrict__ wAll,
              const float* __restrict__ b_cls, const float* __restrict__ b_reg,
              const float* __restrict__ b_ctr,
              float* __restrict__ out_cls, float* __restrict__ out_reg)
{
    constexpr int THREADS = NW * 32;
    // ---- level decode ----
    const int bx = blockIdx.x;
    int l, tile, H, W, wt;
    if (bx < 100)      { l = 0; tile = bx;       H = 100; W = 128; wt = 4; }
    else if (bx < 126) { l = 1; tile = bx - 100; H = 50;  W = 64;  wt = 2; }
    else               { l = 2; tile = bx - 126; H = 25;  W = 32;  wt = 1; }
    const int HW = H * W;
    const long SOFF[3] = { 0L, 26214400L, 32768000L };     // fp32 scratch
    const long POFF[3] = { 0L, 13107200L, 16384000L };     // packed half2
    const int  OOFF[3] = { 0, 12800, 16000 };

    const int tid = threadIdx.x, wid = tid >> 5, lane = tid & 31;
    const int iw = wid & 7;
    const int g = lane >> 2, t = lane & 3;
    const int wm = iw & 3, wn = iw >> 2;
    const int n = blockIdx.z;

    const int tower  = blockIdx.y;
    const int ocTile = (NW == 16) ? (wid >> 3) : 0;
    const int OCv = (STAGE == 2) ? (tower ? 5 : 20) : 256;
    const int ocBase = ocTile * 128;
    const int x0 = (tile % wt) << 5;
    const int y0 = (tile / wt) << 2;
    const bool active = (ocBase + wm * 32) < OCv;

    __shared__ uint32_t halo[2][4080];   // 204 px * 20 words, double-buffered

    const int mm = lane >> 3, rr = lane & 7;
    const uint32_t sbase = smem_u32(halo);
    uint32_t bAddr[4];
#pragma unroll
    for (int p = 0; p < 4; ++p) {
        int pxl = wn * 64 + (2 * p + (mm >> 1)) * 8 + rr;
        bAddr[p] = sbase + (uint32_t)((((pxl >> 5) * 34 + (pxl & 31)) * 20 + (mm & 1) * 4) * 4);
    }

    float acc[2][8][4];
#pragma unroll
    for (int i = 0; i < 2; ++i)
#pragma unroll
        for (int j = 0; j < 8; ++j)
#pragma unroll
            for (int q = 0; q < 4; ++q) acc[i][j][q] = 0.f;

    const uint32_t* __restrict__ inP =
        (tower ? pkReg : pkCls) + POFF[l] + (long)n * 128 * HW;
    const uint32_t* wA;
    if (STAGE == 0)      wA = wAll + tower * 589824;
    else if (STAGE == 1) wA = wAll + tower * 589824 + 294912;
    else                 wA = wAll + 1179648 + tower * 147456;
    const uint4* __restrict__ wf4 = (const uint4*)(wA + (long)ocTile * 147456);

    // one staging item -> one 4B cp.async into halo buffer hb
    auto stage_cp = [&](int chunk, int hb, int i) {
        int w = i / 204; int px = i - w * 204;
        int ri = px / 34, ci = px - ri * 34;
        int ygl = y0 + ri - 1, xgl = x0 + ci - 1;
        bool v = (unsigned)ygl < (unsigned)H && (unsigned)xgl < (unsigned)W;
        const uint32_t* src = inP + ((long)(chunk * 16 + w)) * HW + (v ? (ygl * W + xgl) : 0);
        uint32_t dst = sbase + (uint32_t)hb * 16320u + (uint32_t)(px * 20 + w) * 4;
        CP_A4(dst, src, v ? 4u : 0u);
    };

    // ---- prologue: chunk-0 halo async, tap-0 A fragments ----
    for (int i = tid; i < 3264; i += THREADS) stage_cp(0, 0, i);
    uint4 Ac[4];
    if (active) {
#pragma unroll
        for (int q = 0; q < 4; ++q)
            Ac[q] = wf4[(q >> 1) * 256 + (wm * 2 + (q & 1)) * 32 + lane];
    }
    CP_WAIT_ALL();
    __syncthreads();

    for (int chunk = 0; chunk < 8; ++chunk) {
        const int hb = chunk & 1;
        const uint32_t hoff = (uint32_t)hb * 16320u;
        for (int tap = 0; tap < 9; ++tap) {
            const int cid = chunk * 9 + tap;

            // async staging of next chunk's slice (lands in other buffer)
            if (chunk < 7) {
                int lo = tap * 368;
                int hi = lo + 368; if (hi > 3264) hi = 3264;
                for (int i = lo + tid; i < hi; i += THREADS)
                    stage_cp(chunk + 1, hb ^ 1, i);
            }
            // A prefetch for next tap
            uint4 An[4];
            if (active && cid < 71) {
                const uint4* wf = wf4 + (long)(cid + 1) * 512;
#pragma unroll
                for (int q = 0; q < 4; ++q)
                    An[q] = wf[(q >> 1) * 256 + (wm * 2 + (q & 1)) * 32 + lane];
            }
            // MMA block
            if (active) {
                const uint32_t toff = hoff + (uint32_t)(((tap / 3) * 34 + (tap % 3)) * 80);
#pragma unroll
                for (int ks = 0; ks < 2; ++ks) {
                    const uint32_t o2 = toff + ks * 32;
#pragma unroll
                    for (int p = 0; p < 4; ++p) {
                        uint32_t b[4];
                        ldsm4(b, bAddr[p] + o2);
                        mma16(acc[0][2 * p],     (const uint32_t*)&Ac[ks * 2],     b[0], b[1]);
                        mma16(acc[1][2 * p],     (const uint32_t*)&Ac[ks * 2 + 1], b[0], b[1]);
                        mma16(acc[0][2 * p + 1], (const uint32_t*)&Ac[ks * 2],     b[2], b[3]);
                        mma16(acc[1][2 * p + 1], (const uint32_t*)&Ac[ks * 2 + 1], b[2], b[3]);
                    }
                }
            }
            if (active && cid < 71) {
                Ac[0] = An[0]; Ac[1] = An[1]; Ac[2] = An[2]; Ac[3] = An[3];
            }
        }
        CP_WAIT_ALL();
        __syncthreads();
    }

    if (!active) return;

    // ---- epilogue ----
#pragma unroll
    for (int mbi = 0; mbi < 2; ++mbi) {
        const int ocl = (wm * 2 + mbi) * 16 + g;
        const int oc = ocBase + ocl;
        if (STAGE < 2) {
            float* outBase = (tower ? out_reg : out_cls) + SOFF[l];
            const float* bias = tower ? b_reg : b_cls;
            const float bv0 = bias[oc], bv1 = bias[oc + 8];
            float* o0 = outBase + ((long)n * 256 + oc) * HW;
#pragma unroll
            for (int nb = 0; nb < 8; ++nb) {
                int pxl = wn * 64 + nb * 8 + 2 * t;
                int ygl = y0 + (pxl >> 5);
                if (ygl >= H) continue;
                long idx = (long)ygl * W + x0 + (pxl & 31);
                *(float2*)(o0 + idx) =
                    make_float2(acc[mbi][nb][0] + bv0, acc[mbi][nb][1] + bv0);
                *(float2*)(o0 + 8L * HW + idx) =
                    make_float2(acc[mbi][nb][2] + bv1, acc[mbi][nb][3] + bv1);
            }
        } else if (tower == 0) {   // cls head
            float* out = out_cls;
#pragma unroll
            for (int nb = 0; nb < 8; ++nb) {
                int pxl = wn * 64 + nb * 8 + 2 * t;
                int ygl = y0 + (pxl >> 5);
                if (ygl >= H) continue;
                int pxg = ygl * W + x0 + (pxl & 31);
                long b = ((long)n * NPIX + OOFF[l] + pxg) * 20;
                if (oc < 20) {
                    float bv = b_cls[oc];
                    out[b + oc]      = acc[mbi][nb][0] + bv;
                    out[b + 20 + oc] = acc[mbi][nb][1] + bv;
                }
                if (oc + 8 < 20) {
                    float bv = b_cls[oc + 8];
                    out[b + oc + 8]      = acc[mbi][nb][2] + bv;
                    out[b + 20 + oc + 8] = acc[mbi][nb][3] + bv;
                }
            }
        } else {                   // reg + ctr head
            float* out = out_reg;
#pragma unroll
            for (int nb = 0; nb < 8; ++nb) {
                int pxl = wn * 64 + nb * 8 + 2 * t;
                int ygl = y0 + (pxl >> 5);
                if (ygl >= H) continue;
                int pxg = ygl * W + x0 + (pxl & 31);
#pragma unroll
                for (int rrj = 0; rrj < 2; ++rrj) {
                    int ocr = oc + rrj * 8;
                    float v0 = acc[mbi][nb][rrj * 2 + 0];
                    float v1 = acc[mbi][nb][rrj * 2 + 1];
                    if (ocr < 4) {
                        float bv = b_reg[ocr];
                        long rb = REG_BASE + (long)n * 67200 + (long)(OOFF[l] + pxg) * 4 + ocr;
                        out[rb]     = fmaxf(v0 + bv, 0.f);
                        out[rb + 4] = fmaxf(v1 + bv, 0.f);
                    } else if (ocr == 4) {
                        float bv = b_ctr[0];
                        long cb = CTR_BASE + (long)n * NPIX + OOFF[l] + pxg;
                        out[cb]     = v0 + bv;
                        out[cb + 1] = v1 + bv;
                    }
                }
            }
        }
    }
}

// ---------------------------------------------------------------------------
// Packing passes: fp32 NCHW -> half2 [n][chunk*16+w][HW] (pair = channels
// 2cw, 2cw+1). cvt_feat: plain convert (tower-shared). cvt_gn: GN+ReLU then
// convert (same fp32 math as before => bit-identical results).
// ---------------------------------------------------------------------------
__global__ void cvt_feat(const float* __restrict__ f0, const float* __restrict__ f1,
                         const float* __restrict__ f2, uint32_t* __restrict__ outP)
{
    long id = (long)blockIdx.x * 256 + threadIdx.x;
    if (id >= 17203200L) return;
    long idx; const float* f; int HW;
    if (id < 13107200L)      { idx = id;             f = f0; HW = 12800; }
    else if (id < 16384000L) { idx = id - 13107200L; f = f1; HW = 3200; }
    else                     { idx = id - 16384000L; f = f2; HW = 800; }
    int px = (int)(idx % HW);
    long q = idx / HW;
    int cw = (int)(q & 127);
    int n  = (int)(q >> 7);
    const float* p = f + ((long)(n * 256 + 2 * cw)) * HW + px;
    __half2 h = __floats2half2_rn(p[0], p[HW]);
    outP[id] = *(uint32_t*)&h;
}

__global__ void cvt_gn(const float* __restrict__ bufCls, const float* __restrict__ bufReg,
                       const float* __restrict__ gcls, const float* __restrict__ bcls,
                       const float* __restrict__ greg, const float* __restrict__ breg,
                       uint32_t* __restrict__ outCls, uint32_t* __restrict__ outReg)
{
    long id = (long)blockIdx.x * 256 + threadIdx.x;
    if (id >= 34406400L) return;
    int tower = id >= 17203200L;
    long rid = tower ? id - 17203200L : id;
    int l; long idx; int HW; long soff;
    if (rid < 13107200L)      { l = 0; idx = rid;             HW = 12800; soff = 0L; }
    else if (rid < 16384000L) { l = 1; idx = rid - 13107200L; HW = 3200;  soff = 26214400L; }
    else                      { l = 2; idx = rid - 16384000L; HW = 800;   soff = 32768000L; }
    int px = (int)(idx % HW);
    long q = idx / HW;
    int cw = (int)(q & 127);
    int n  = (int)(q >> 7);
    int c = 2 * cw;
    const float* in = (tower ? bufReg : bufCls) + soff + ((long)(n * 256 + c)) * HW + px;
    const float* ga = tower ? greg : gcls;
    const float* be = tower ? breg : bcls;
    int sg = (tower * 3 + l) * 128 + n * 16 + (c >> 4);
    float m = g_mean[sg], rs = g_rstd[sg];
    float v0 = fmaxf((in[0]  - m) * rs * ga[c]     + be[c],     0.f);
    float v1 = fmaxf((in[HW] - m) * rs * ga[c + 1] + be[c + 1], 0.f);
    __half2 h = __floats2half2_rn(v0, v1);
    (tower ? outReg : outCls)[rid] = *(uint32_t*)&h;
}

// ---------------------------------------------------------------------------
// Weight reorders -> fragment-linear half2 (unchanged layout).
// ---------------------------------------------------------------------------
__device__ __forceinline__ void frag_decode(int d, int& r, int& chunk, int& tap,
                                            int& oc128, int& icp)
{
    int j = d & 3; int q = d >> 2;
    int lane = q & 31; q >>= 5;
    int mb = q & 7;  q >>= 3;
    int ks = q & 1;  q >>= 1;
    tap = q % 9; q /= 9;
    chunk = q & 7; q >>= 3;
    r = q;
    oc128 = mb * 16 + (lane >> 2) + (j & 1) * 8;
    icp   = chunk * 32 + ks * 16 + (lane & 3) * 2 + ((j >> 1) & 1) * 8;
}

__global__ void reorder_tower(const float* __restrict__ w, uint32_t* __restrict__ dst)
{
    int d = blockIdx.x * 256 + threadIdx.x;
    if (d >= 589824) return;
    int r, chunk, tap, oc128, icp;
    frag_decode(d, r, chunk, tap, oc128, icp);
    int layer = r >> 1;
    int oc = (r & 1) * 128 + oc128;
    const float* src = w + (long)layer * 589824;
    float v0 = src[((long)oc * 256 + icp) * 9 + tap];
    float v1 = src[((long)oc * 256 + icp + 1) * 9 + tap];
    __half2 h = __floats2half2_rn(v0, v1);
    dst[d] = *(uint32_t*)&h;
}

__global__ void reorder_heads(const float* __restrict__ wcls, const float* __restrict__ wreg,
                              const float* __restrict__ wctr, uint32_t* __restrict__ dst)
{
    int d = blockIdx.x * 256 + threadIdx.x;
    if (d >= 294912) return;
    int r, chunk, tap, oc128, icp;
    frag_decode(d, r, chunk, tap, oc128, icp);
    int oc = oc128;
    float v0 = 0.f, v1 = 0.f;
    if (r == 0) {
        if (oc < 20) {
            v0 = wcls[((long)oc * 256 + icp) * 9 + tap];
            v1 = wcls[((long)oc * 256 + icp + 1) * 9 + tap];
        }
    } else {
        if (oc < 4) {
            v0 = wreg[((long)oc * 256 + icp) * 9 + tap];
            v1 = wreg[((long)oc * 256 + icp + 1) * 9 + tap];
        } else if (oc == 4) {
            v0 = wctr[(long)icp * 9 + tap];
            v1 = wctr[(long)(icp + 1) * 9 + tap];
        }
    }
    __half2 h = __floats2half2_rn(v0, v1);
    dst[d] = *(uint32_t*)&h;
}

// ---------------------------------------------------------------------------
// GroupNorm stats for all (tower, level) pairs in one launch.
// ---------------------------------------------------------------------------
__global__ void gn_stats_all(const float* __restrict__ bufCls, const float* __restrict__ bufReg)
{
    const int by = blockIdx.y;
    const int tower = by / 3, l = by - tower * 3;
    const int HWs[3] = { 12800, 3200, 800 };
    const long SOFF[3] = { 0L, 26214400L, 32768000L };
    const int HW = HWs[l];
    const int n = blockIdx.x >> 4;
    const int g = blockIdx.x & 15;
    const float4* p = (const float4*)((tower ? bufReg : bufCls) + SOFF[l]
                                      + ((long)n * 256 + (long)g * 16) * HW);
    const int total4 = (16 * HW) >> 2;
    float s = 0.f, s2 = 0.f;
    for (int i = threadIdx.x; i < total4; i += blockDim.x) {
        float4 v = p[i];
        s  += v.x + v.y + v.z + v.w;
        s2 += v.x * v.x + v.y * v.y + v.z * v.z + v.w * v.w;
    }
    __shared__ float rs[8], rs2[8];
#pragma unroll
    for (int o = 16; o; o >>= 1) {
        s  += __shfl_xor_sync(~0u, s, o);
        s2 += __shfl_xor_sync(~0u, s2, o);
    }
    const int w = threadIdx.x >> 5, lid = threadIdx.x & 31;
    if (lid == 0) { rs[w] = s; rs2[w] = s2; }
    __syncthreads();
    if (w == 0) {
        s  = (lid < 8) ? rs[lid]  : 0.f;
        s2 = (lid < 8) ? rs2[lid] : 0.f;
#pragma unroll
        for (int o = 4; o; o >>= 1) {
            s  += __shfl_xor_sync(~0u, s, o);
            s2 += __shfl_xor_sync(~0u, s2, o);
        }
        if (lid == 0) {
            float inv = 1.f / (float)(16 * HW);
            float m = s * inv;
            g_mean[by * 128 + blockIdx.x] = m;
            g_rstd[by * 128 + blockIdx.x] = rsqrtf(s2 * inv - m * m + 1e-5f);
        }
    }
}

// ---------------------------------------------------------------------------
extern "C" void kernel_launch(void* const* d_in, const int* in_sizes, int n_in,
                              void* d_out, int out_size)
{
    (void)in_sizes; (void)n_in; (void)out_size;
    const float* feat0 = (const float*)d_in[0];
    const float* feat1 = (const float*)d_in[1];
    const float* feat2 = (const float*)d_in[2];
    const float* cls_conv_w = (const float*)d_in[3];
    const float* cls_conv_b = (const float*)d_in[4];
    const float* cls_gn_g = (const float*)d_in[5];
    const float* cls_gn_b = (const float*)d_in[6];
    const float* cls_out_w = (const float*)d_in[7];
    const float* cls_out_b = (const float*)d_in[8];
    const float* reg_conv_w = (const float*)d_in[9];
    const float* reg_conv_b = (const float*)d_in[10];
    const float* reg_gn_g = (const float*)d_in[11];
    const float* reg_gn_b = (const float*)d_in[12];
    const float* reg_out_w = (const float*)d_in[13];
    const float* reg_out_b = (const float*)d_in[14];
    const float* ctr_w = (const float*)d_in[15];
    const float* ctr_b = (const float*)d_in[16];
    float* out = (float*)d_out;

    float *pA, *pB, *pC, *pD;
    uint32_t *pW, *pPF, *pP1c, *pP1r, *pP2c, *pP2r;
    cudaGetSymbolAddress((void**)&pA, g_A);
    cudaGetSymbolAddress((void**)&pB, g_B);
    cudaGetSymbolAddress((void**)&pC, g_C);
    cudaGetSymbolAddress((void**)&pD, g_D);
    cudaGetSymbolAddress((void**)&pW, g_W);
    cudaGetSymbolAddress((void**)&pPF, g_PF);
    cudaGetSymbolAddress((void**)&pP1c, g_P1c);
    cudaGetSymbolAddress((void**)&pP1r, g_P1r);
    cudaGetSymbolAddress((void**)&pP2c, g_P2c);
    cudaGetSymbolAddress((void**)&pP2r, g_P2r);

    // weight reorders + feat packing
    reorder_tower<<<2304, 256>>>(cls_conv_w, pW);
    reorder_tower<<<2304, 256>>>(reg_conv_w, pW + 589824);
    reorder_heads<<<1152, 256>>>(cls_out_w, reg_out_w, ctr_w, pW + 1179648);
    cvt_feat<<<67200, 256>>>(feat0, feat1, feat2, pPF);

    // stage 1: conv1 (both towers read shared packed feats)
    conv_mma<0, 16><<<dim3(133, 2, 8), 512>>>(pPF, pPF, pW,
                                              cls_conv_b, reg_conv_b, nullptr, pA, pC);
    gn_stats_all<<<dim3(128, 6), 256>>>(pA, pC);
    cvt_gn<<<134400, 256>>>(pA, pC, cls_gn_g, cls_gn_b, reg_gn_g, reg_gn_b, pP1c, pP1r);

    // stage 2: conv2
    conv_mma<1, 16><<<dim3(133, 2, 8), 512>>>(pP1c, pP1r, pW,
                                              cls_conv_b + 256, reg_conv_b + 256, nullptr,
                                              pB, pD);
    gn_stats_all<<<dim3(128, 6), 256>>>(pB, pD);
    cvt_gn<<<134400, 256>>>(pB, pD, cls_gn_g + 256, cls_gn_b + 256,
                            reg_gn_g + 256, reg_gn_b + 256, pP2c, pP2r);

    // stage 3: heads
    conv_mma<2, 8><<<dim3(133, 2, 8), 256>>>(pP2c, pP2r, pW,
                                             cls_out_b, reg_out_b, ctr_b, out, out);
}

// round 16
// speedup vs baseline: 1.7727x; 1.0671x over previous
#include <cuda_runtime.h>
#include <cuda_fp16.h>
#include <stdint.h>

#define NPIX 16800
#define REG_BASE 2688000L
#define CTR_BASE 3225600L

// static device scratch (no cudaMalloc anywhere)
#define BUF_FLOATS 34406400L
__device__ float    g_A[BUF_FLOATS];    // cls conv1 fp32 out
__device__ float    g_B[BUF_FLOATS];    // cls conv2 fp32 out
__device__ float    g_C[BUF_FLOATS];    // reg conv1 fp32 out
__device__ float    g_D[BUF_FLOATS];    // reg conv2 fp32 out
__device__ uint32_t g_PF [17203200];    // packed half2 feats (tower-shared)
__device__ uint32_t g_P1c[17203200];    // packed GN(conv1) cls
__device__ uint32_t g_P1r[17203200];    // packed GN(conv1) reg
__device__ uint32_t g_P2c[17203200];    // packed GN(conv2) cls
__device__ uint32_t g_P2r[17203200];    // packed GN(conv2) reg
__device__ uint32_t g_W[1474560];       // fragment-ordered half2 weights
__device__ float    g_part[68096];      // per-CTA GN partials [2128][16grp][2]
__device__ float    g_mean[768];        // [tower*3+level][n*16+g]
__device__ float    g_rstd[768];

__device__ __forceinline__ uint32_t smem_u32(const void* p) {
    uint32_t a;
    asm("{ .reg .u64 t; cvta.to.shared.u64 t, %1; cvt.u32.u64 %0, t; }" : "=r"(a) : "l"(p));
    return a;
}
__device__ __forceinline__ void mma16(float* c, const uint32_t* a, uint32_t b0, uint32_t b1) {
    asm volatile(
        "mma.sync.aligned.m16n8k16.row.col.f32.f16.f16.f32 "
        "{%0,%1,%2,%3}, {%4,%5,%6,%7}, {%8,%9}, {%0,%1,%2,%3};"
        : "+f"(c[0]), "+f"(c[1]), "+f"(c[2]), "+f"(c[3])
        : "r"(a[0]), "r"(a[1]), "r"(a[2]), "r"(a[3]), "r"(b0), "r"(b1));
}
__device__ __forceinline__ void ldsm4(uint32_t* r, uint32_t addr) {
    asm volatile("ldmatrix.sync.aligned.m8n8.x4.shared.b16 {%0,%1,%2,%3}, [%4];"
        : "=r"(r[0]), "=r"(r[1]), "=r"(r[2]), "=r"(r[3]) : "r"(addr));
}
#define CP_A4(dst, src, sz) \
    asm volatile("cp.async.ca.shared.global [%0], [%1], 4, %2;" \
                 :: "r"(dst), "l"(src), "r"(sz) : "memory")
#define CP_WAIT_ALL() asm volatile("cp.async.wait_all;" ::: "memory")

// ---------------------------------------------------------------------------
// Merged fp16 mma.sync conv3x3 s1p1, cp.async halo staging (R13 core).
// R14/15: tower-stage epilogue ALSO emits per-CTA GN partial sums
// (deterministic warp-shfl + smem reduction into g_part); the standalone
// gn_stats passes are gone. gn_finalize sums partials in fixed order.
//  STAGE 0/1: conv -> fp32 NCHW scratch + partials. STAGE 2: heads.
// ---------------------------------------------------------------------------
template<int STAGE, int NW>
__global__ __launch_bounds__(NW * 32, NW == 8 ? 2 : 1)
void conv_mma(const uint32_t* __restrict__ pkCls, const uint32_t* __restrict__ pkReg,
              const uint32_t* __restrict__ wAll,
              const float* __restrict__ b_cls, const float* __restrict__ b_reg,
              const float* __restrict__ b_ctr,
              float* __restrict__ out_cls, float* __restrict__ out_reg)
{
    constexpr int THREADS = NW * 32;
    const int bx = blockIdx.x;
    int l, tile, H, W, wt;
    if (bx < 100)      { l = 0; tile = bx;       H = 100; W = 128; wt = 4; }
    else if (bx < 126) { l = 1; tile = bx - 100; H = 50;  W = 64;  wt = 2; }
    else               { l = 2; tile = bx - 126; H = 25;  W = 32;  wt = 1; }
    const int HW = H * W;
    const long SOFF[3] = { 0L, 26214400L, 32768000L };
    const long POFF[3] = { 0L, 13107200L, 16384000L };
    const int  OOFF[3] = { 0, 12800, 16000 };

    const int tid = threadIdx.x, wid = tid >> 5, lane = tid & 31;
    const int iw = wid & 7;
    const int g = lane >> 2, t = lane & 3;
    const int wm = iw & 3, wn = iw >> 2;
    const int n = blockIdx.z;

    const int tower  = blockIdx.y;
    const int ocTile = (NW == 16) ? (wid >> 3) : 0;
    const int OCv = (STAGE == 2) ? (tower ? 5 : 20) : 256;
    const int ocBase = ocTile * 128;
    const int x0 = (tile % wt) << 5;
    const int y0 = (tile / wt) << 2;
    const bool active = (ocBase + wm * 32) < OCv;

    __shared__ uint32_t halo[2][4080];

    const int mm = lane >> 3, rr = lane & 7;
    const uint32_t sbase = smem_u32(halo);
    uint32_t bAddr[4];
#pragma unroll
    for (int p = 0; p < 4; ++p) {
        int pxl = wn * 64 + (2 * p + (mm >> 1)) * 8 + rr;
        bAddr[p] = sbase + (uint32_t)((((pxl >> 5) * 34 + (pxl & 31)) * 20 + (mm & 1) * 4) * 4);
    }

    float acc[2][8][4];
#pragma unroll
    for (int i = 0; i < 2; ++i)
#pragma unroll
        for (int j = 0; j < 8; ++j)
#pragma unroll
            for (int q = 0; q < 4; ++q) acc[i][j][q] = 0.f;

    const uint32_t* __restrict__ inP =
        (tower ? pkReg : pkCls) + POFF[l] + (long)n * 128 * HW;
    const uint32_t* wA;
    if (STAGE == 0)      wA = wAll + tower * 589824;
    else if (STAGE == 1) wA = wAll + tower * 589824 + 294912;
    else                 wA = wAll + 1179648 + tower * 147456;
    const uint4* __restrict__ wf4 = (const uint4*)(wA + (long)ocTile * 147456);

    auto stage_cp = [&](int chunk, int hb, int i) {
        int w = i / 204; int px = i - w * 204;
        int ri = px / 34, ci = px - ri * 34;
        int ygl = y0 + ri - 1, xgl = x0 + ci - 1;
        bool v = (unsigned)ygl < (unsigned)H && (unsigned)xgl < (unsigned)W;
        const uint32_t* src = inP + ((long)(chunk * 16 + w)) * HW + (v ? (ygl * W + xgl) : 0);
        uint32_t dst = sbase + (uint32_t)hb * 16320u + (uint32_t)(px * 20 + w) * 4;
        CP_A4(dst, src, v ? 4u : 0u);
    };

    for (int i = tid; i < 3264; i += THREADS) stage_cp(0, 0, i);
    uint4 Ac[4];
    if (active) {
#pragma unroll
        for (int q = 0; q < 4; ++q)
            Ac[q] = wf4[(q >> 1) * 256 + (wm * 2 + (q & 1)) * 32 + lane];
    }
    CP_WAIT_ALL();
    __syncthreads();

    for (int chunk = 0; chunk < 8; ++chunk) {
        const int hb = chunk & 1;
        const uint32_t hoff = (uint32_t)hb * 16320u;
        for (int tap = 0; tap < 9; ++tap) {
            const int cid = chunk * 9 + tap;
            if (chunk < 7) {
                int lo = tap * 368;
                int hi = lo + 368; if (hi > 3264) hi = 3264;
                for (int i = lo + tid; i < hi; i += THREADS)
                    stage_cp(chunk + 1, hb ^ 1, i);
            }
            uint4 An[4];
            if (active && cid < 71) {
                const uint4* wf = wf4 + (long)(cid + 1) * 512;
#pragma unroll
                for (int q = 0; q < 4; ++q)
                    An[q] = wf[(q >> 1) * 256 + (wm * 2 + (q & 1)) * 32 + lane];
            }
            if (active) {
                const uint32_t toff = hoff + (uint32_t)(((tap / 3) * 34 + (tap % 3)) * 80);
#pragma unroll
                for (int ks = 0; ks < 2; ++ks) {
                    const uint32_t o2 = toff + ks * 32;
#pragma unroll
                    for (int p = 0; p < 4; ++p) {
                        uint32_t b[4];
                        ldsm4(b, bAddr[p] + o2);
                        mma16(acc[0][2 * p],     (const uint32_t*)&Ac[ks * 2],     b[0], b[1]);
                        mma16(acc[1][2 * p],     (const uint32_t*)&Ac[ks * 2 + 1], b[0], b[1]);
                        mma16(acc[0][2 * p + 1], (const uint32_t*)&Ac[ks * 2],     b[2], b[3]);
                        mma16(acc[1][2 * p + 1], (const uint32_t*)&Ac[ks * 2 + 1], b[2], b[3]);
                    }
                }
            }
            if (active && cid < 71) {
                Ac[0] = An[0]; Ac[1] = An[1]; Ac[2] = An[2]; Ac[3] = An[3];
            }
        }
        CP_WAIT_ALL();
        __syncthreads();
    }

    if (STAGE == 2 && !active) return;

    // ---- epilogue (+ GN partials for tower stages) ----
    float ps[2] = { 0.f, 0.f }, pq[2] = { 0.f, 0.f };
#pragma unroll
    for (int mbi = 0; mbi < 2; ++mbi) {
        const int ocl = (wm * 2 + mbi) * 16 + g;
        const int oc = ocBase + ocl;
        if (STAGE < 2) {
            float* outBase = (tower ? out_reg : out_cls) + SOFF[l];
            const float* bias = tower ? b_reg : b_cls;
            const float bv0 = bias[oc], bv1 = bias[oc + 8];
            float* o0 = outBase + ((long)n * 256 + oc) * HW;
#pragma unroll
            for (int nb = 0; nb < 8; ++nb) {
                int pxl = wn * 64 + nb * 8 + 2 * t;
                int ygl = y0 + (pxl >> 5);
                if (ygl >= H) continue;
                long idx = (long)ygl * W + x0 + (pxl & 31);
                float v0 = acc[mbi][nb][0] + bv0, v1 = acc[mbi][nb][1] + bv0;
                float v2 = acc[mbi][nb][2] + bv1, v3 = acc[mbi][nb][3] + bv1;
                *(float2*)(o0 + idx)           = make_float2(v0, v1);
                *(float2*)(o0 + 8L * HW + idx) = make_float2(v2, v3);
                ps[mbi] += (v0 + v1) + (v2 + v3);
                pq[mbi] += (v0 * v0 + v1 * v1) + (v2 * v2 + v3 * v3);
            }
        } else if (tower == 0) {   // cls head
            float* out = out_cls;
#pragma unroll
            for (int nb = 0; nb < 8; ++nb) {
                int pxl = wn * 64 + nb * 8 + 2 * t;
                int ygl = y0 + (pxl >> 5);
                if (ygl >= H) continue;
                int pxg = ygl * W + x0 + (pxl & 31);
                long b = ((long)n * NPIX + OOFF[l] + pxg) * 20;
                if (oc < 20) {
                    float bv = b_cls[oc];
                    out[b + oc]      = acc[mbi][nb][0] + bv;
                    out[b + 20 + oc] = acc[mbi][nb][1] + bv;
                }
                if (oc + 8 < 20) {
                    float bv = b_cls[oc + 8];
                    out[b + oc + 8]      = acc[mbi][nb][2] + bv;
                    out[b + 20 + oc + 8] = acc[mbi][nb][3] + bv;
                }
            }
        } else {                   // reg + ctr head
            float* out = out_reg;
#pragma unroll
            for (int nb = 0; nb < 8; ++nb) {
                int pxl = wn * 64 + nb * 8 + 2 * t;
                int ygl = y0 + (pxl >> 5);
                if (ygl >= H) continue;
                int pxg = ygl * W + x0 + (pxl & 31);
#pragma unroll
                for (int rrj = 0; rrj < 2; ++rrj) {
                    int ocr = oc + rrj * 8;
                    float v0 = acc[mbi][nb][rrj * 2 + 0];
                    float v1 = acc[mbi][nb][rrj * 2 + 1];
                    if (ocr < 4) {
                        float bv = b_reg[ocr];
                        long rb = REG_BASE + (long)n * 67200 + (long)(OOFF[l] + pxg) * 4 + ocr;
                        out[rb]     = fmaxf(v0 + bv, 0.f);
                        out[rb + 4] = fmaxf(v1 + bv, 0.f);
                    } else if (ocr == 4) {
                        float bv = b_ctr[0];
                        long cb = CTR_BASE + (long)n * NPIX + OOFF[l] + pxg;
                        out[cb]     = v0 + bv;
                        out[cb + 1] = v1 + bv;
                    }
                }
            }
        }
    }

    if (STAGE < 2) {
        // warp reduce (deterministic)
#pragma unroll
        for (int o = 16; o; o >>= 1) {
            ps[0] += __shfl_xor_sync(~0u, ps[0], o);
            pq[0] += __shfl_xor_sync(~0u, pq[0], o);
            ps[1] += __shfl_xor_sync(~0u, ps[1], o);
            pq[1] += __shfl_xor_sync(~0u, pq[1], o);
        }
        float* sred = (float*)halo;      // halo is dead now
        if (lane == 0) {
            sred[wid * 4 + 0] = ps[0]; sred[wid * 4 + 1] = pq[0];
            sred[wid * 4 + 2] = ps[1]; sred[wid * 4 + 3] = pq[1];
        }
        __syncthreads();
        if (tid < 16) {
            int oct = tid >> 3, wmm = (tid >> 1) & 3, mbi = tid & 1;
            int w0 = oct * 8 + wmm;
            float s  = sred[w0 * 4 + 2 * mbi]     + sred[(w0 + 4) * 4 + 2 * mbi];
            float s2 = sred[w0 * 4 + 2 * mbi + 1] + sred[(w0 + 4) * 4 + 2 * mbi + 1];
            int grp = oct * 8 + wmm * 2 + mbi;
            long bLin = bx + 133L * (tower + 2L * n);
            g_part[bLin * 32 + grp * 2]     = s;
            g_part[bLin * 32 + grp * 2 + 1] = s2;
        }
    }
}

// ---------------------------------------------------------------------------
// GN finalize: fixed-order sum of per-CTA partials -> mean/rstd. 768 entries.
// ---------------------------------------------------------------------------
__global__ void gn_finalize()
{
    int id = blockIdx.x * 256 + threadIdx.x;
    if (id >= 768) return;
    int by = id >> 7;                  // tower*3 + l
    int tower = by / 3, l = by - tower * 3;
    int idx = id & 127;
    int n = idx >> 4, grp = idx & 15;
    const int LO[3] = { 0, 100, 126 }, HI[3] = { 100, 126, 133 };
    const int HWs[3] = { 12800, 3200, 800 };
    float s = 0.f, s2 = 0.f;
    for (int bxx = LO[l]; bxx < HI[l]; ++bxx) {
        long bLin = bxx + 133L * (tower + 2L * n);
        s  += g_part[bLin * 32 + grp * 2];
        s2 += g_part[bLin * 32 + grp * 2 + 1];
    }
    float inv = 1.f / (float)(16 * HWs[l]);
    float m = s * inv;
    g_mean[id] = m;
    g_rstd[id] = rsqrtf(s2 * inv - m * m + 1e-5f);
}

// ---------------------------------------------------------------------------
// Packing passes (unchanged from R13)
// ---------------------------------------------------------------------------
__global__ void cvt_feat(const float* __restrict__ f0, const float* __restrict__ f1,
                         const float* __restrict__ f2, uint32_t* __restrict__ outP)
{
    long id = (long)blockIdx.x * 256 + threadIdx.x;
    if (id >= 17203200L) return;
    long idx; const float* f; int HW;
    if (id < 13107200L)      { idx = id;             f = f0; HW = 12800; }
    else if (id < 16384000L) { idx = id - 13107200L; f = f1; HW = 3200; }
    else                     { idx = id - 16384000L; f = f2; HW = 800; }
    int px = (int)(idx % HW);
    long q = idx / HW;
    int cw = (int)(q & 127);
    int n  = (int)(q >> 7);
    const float* p = f + ((long)(n * 256 + 2 * cw)) * HW + px;
    __half2 h = __floats2half2_rn(p[0], p[HW]);
    outP[id] = *(uint32_t*)&h;
}

__global__ void cvt_gn(const float* __restrict__ bufCls, const float* __restrict__ bufReg,
                       const float* __restrict__ gcls, const float* __restrict__ bcls,
                       const float* __restrict__ greg, const float* __restrict__ breg,
                       uint32_t* __restrict__ outCls, uint32_t* __restrict__ outReg)
{
    long id = (long)blockIdx.x * 256 + threadIdx.x;
    if (id >= 34406400L) return;
    int tower = id >= 17203200L;
    long rid = tower ? id - 17203200L : id;
    int l; long idx; int HW; long soff;
    if (rid < 13107200L)      { l = 0; idx = rid;             HW = 12800; soff = 0L; }
    else if (rid < 16384000L) { l = 1; idx = rid - 13107200L; HW = 3200;  soff = 26214400L; }
    else                      { l = 2; idx = rid - 16384000L; HW = 800;   soff = 32768000L; }
    int px = (int)(idx % HW);
    long q = idx / HW;
    int cw = (int)(q & 127);
    int n  = (int)(q >> 7);
    int c = 2 * cw;
    const float* in = (tower ? bufReg : bufCls) + soff + ((long)(n * 256 + c)) * HW + px;
    const float* ga = tower ? greg : gcls;
    const float* be = tower ? breg : bcls;
    int sg = (tower * 3 + l) * 128 + n * 16 + (c >> 4);
    float m = g_mean[sg], rs = g_rstd[sg];
    float v0 = fmaxf((in[0]  - m) * rs * ga[c]     + be[c],     0.f);
    float v1 = fmaxf((in[HW] - m) * rs * ga[c + 1] + be[c + 1], 0.f);
    __half2 h = __floats2half2_rn(v0, v1);
    (tower ? outReg : outCls)[rid] = *(uint32_t*)&h;
}

// ---------------------------------------------------------------------------
// Single merged weight reorder (fragment-linear half2, same layout).
// ---------------------------------------------------------------------------
__device__ __forceinline__ void frag_decode(int d, int& r, int& chunk, int& tap,
                                            int& oc128, int& icp)
{
    int j = d & 3; int q = d >> 2;
    int lane = q & 31; q >>= 5;
    int mb = q & 7;  q >>= 3;
    int ks = q & 1;  q >>= 1;
    tap = q % 9; q /= 9;
    chunk = q & 7; q >>= 3;
    r = q;
    oc128 = mb * 16 + (lane >> 2) + (j & 1) * 8;
    icp   = chunk * 32 + ks * 16 + (lane & 3) * 2 + ((j >> 1) & 1) * 8;
}

__global__ void reorder_all(const float* __restrict__ wclsT, const float* __restrict__ wregT,
                            const float* __restrict__ wcls, const float* __restrict__ wreg,
                            const float* __restrict__ wctr, uint32_t* __restrict__ dst)
{
    int d0 = blockIdx.x * 256 + threadIdx.x;
    if (d0 >= 1474560) return;
    float v0 = 0.f, v1 = 0.f;
    if (d0 < 1179648) {
        const float* wT = (d0 < 589824) ? wclsT : wregT;
        int d = (d0 < 589824) ? d0 : d0 - 589824;
        int r, chunk, tap, oc128, icp;
        frag_decode(d, r, chunk, tap, oc128, icp);
        int layer = r >> 1;
        int oc = (r & 1) * 128 + oc128;
        const float* src = wT + (long)layer * 589824;
        v0 = src[((long)oc * 256 + icp) * 9 + tap];
        v1 = src[((long)oc * 256 + icp + 1) * 9 + tap];
    } else {
        int d = d0 - 1179648;
        int r, chunk, tap, oc128, icp;
        frag_decode(d, r, chunk, tap, oc128, icp);
        int oc = oc128;
        if (r == 0) {
            if (oc < 20) {
                v0 = wcls[((long)oc * 256 + icp) * 9 + tap];
                v1 = wcls[((long)oc * 256 + icp + 1) * 9 + tap];
            }
        } else {
            if (oc < 4) {
                v0 = wreg[((long)oc * 256 + icp) * 9 + tap];
                v1 = wreg[((long)oc * 256 + icp + 1) * 9 + tap];
            } else if (oc == 4) {
                v0 = wctr[(long)icp * 9 + tap];
                v1 = wctr[(long)(icp + 1) * 9 + tap];
            }
        }
    }
    __half2 h = __floats2half2_rn(v0, v1);
    dst[d0] = *(uint32_t*)&h;
}

// ---------------------------------------------------------------------------
extern "C" void kernel_launch(void* const* d_in, const int* in_sizes, int n_in,
                              void* d_out, int out_size)
{
    (void)in_sizes; (void)n_in; (void)out_size;
    const float* feat0 = (const float*)d_in[0];
    const float* feat1 = (const float*)d_in[1];
    const float* feat2 = (const float*)d_in[2];
    const float* cls_conv_w = (const float*)d_in[3];
    const float* cls_conv_b = (const float*)d_in[4];
    const float* cls_gn_g = (const float*)d_in[5];
    const float* cls_gn_b = (const float*)d_in[6];
    const float* cls_out_w = (const float*)d_in[7];
    const float* cls_out_b = (const float*)d_in[8];
    const float* reg_conv_w = (const float*)d_in[9];
    const float* reg_conv_b = (const float*)d_in[10];
    const float* reg_gn_g = (const float*)d_in[11];
    const float* reg_gn_b = (const float*)d_in[12];
    const float* reg_out_w = (const float*)d_in[13];
    const float* reg_out_b = (const float*)d_in[14];
    const float* ctr_w = (const float*)d_in[15];
    const float* ctr_b = (const float*)d_in[16];
    float* out = (float*)d_out;

    float *pA, *pB, *pC, *pD;
    uint32_t *pW, *pPF, *pP1c, *pP1r, *pP2c, *pP2r;
    cudaGetSymbolAddress((void**)&pA, g_A);
    cudaGetSymbolAddress((void**)&pB, g_B);
    cudaGetSymbolAddress((void**)&pC, g_C);
    cudaGetSymbolAddress((void**)&pD, g_D);
    cudaGetSymbolAddress((void**)&pW, g_W);
    cudaGetSymbolAddress((void**)&pPF, g_PF);
    cudaGetSymbolAddress((void**)&pP1c, g_P1c);
    cudaGetSymbolAddress((void**)&pP1r, g_P1r);
    cudaGetSymbolAddress((void**)&pP2c, g_P2c);
    cudaGetSymbolAddress((void**)&pP2r, g_P2r);

    // launch 1-2: setup
    reorder_all<<<5760, 256>>>(cls_conv_w, reg_conv_w, cls_out_w, reg_out_w, ctr_w, pW);
    cvt_feat<<<67200, 256>>>(feat0, feat1, feat2, pPF);

    // launch 3-5: conv1 (+partials), finalize, pack GN
    conv_mma<0, 16><<<dim3(133, 2, 8), 512>>>(pPF, pPF, pW,
                                              cls_conv_b, reg_conv_b, nullptr, pA, pC);
    gn_finalize<<<3, 256>>>();
    cvt_gn<<<134400, 256>>>(pA, pC, cls_gn_g, cls_gn_b, reg_gn_g, reg_gn_b, pP1c, pP1r);

    // launch 6-8: conv2 (ncu lands here), finalize, pack GN
    conv_mma<1, 16><<<dim3(133, 2, 8), 512>>>(pP1c, pP1r, pW,
                                              cls_conv_b + 256, reg_conv_b + 256, nullptr,
                                              pB, pD);
    gn_finalize<<<3, 256>>>();
    cvt_gn<<<134400, 256>>>(pB, pD, cls_gn_g + 256, cls_gn_b + 256,
                            reg_gn_g + 256, reg_gn_b + 256, pP2c, pP2r);

    // launch 9: heads
    conv_mma<2, 8><<<dim3(133, 2, 8), 256>>>(pP2c, pP2r, pW,
                                             cls_out_b, reg_out_b, ctr_b, out, out);
}